// round 10
// baseline (speedup 1.0000x reference)
#include <cuda_runtime.h>

// Problem constants (fixed shapes)
#define DIM      64
#define NS       16
#define PP       16          // points per tile
#define TPB      4           // tiles per block (main kernel)
#define NTHREADS 256
#define NPTS     16384
#define NB       4
#define QSCALE   0.125f      // 64^-0.5

// ---------------- device scratch (static; no runtime alloc) ----------------
__device__ float g_qk[(size_t)NB * NPTS * DIM];   // [b][n][c]  = W_k^T q * scale
__device__ float g_qp[(size_t)NB * NPTS * 4];     // [b][n][d]  = (W_k W_pos)^T q * scale
__device__ float g_qb[(size_t)NB * NPTS];         // [b][n]     = q . (W_k b_pos) * scale

// ============================================================================
// K1: per-point precompute of qk / qp / qb
// ============================================================================
__global__ void __launch_bounds__(256, 2)
k_precompute(const float* __restrict__ point,   // [B,C,N]
             const float* __restrict__ w_k,     // [64,64] [o][c]
             const float* __restrict__ w_pos,   // [64,4]  [c][d]
             const float* __restrict__ b_pos)   // [64]
{
    __shared__ float wks[4096];   // [o*64+c] unpadded (broadcast reads only)
    __shared__ float wps[256];    // [c*4+d]
    __shared__ float bps[64];
    __shared__ float Ms[256];     // M = W_k * W_pos  [o*4+d]
    __shared__ float bbs[64];     // bb = W_k * b_pos [o]

    const int tid = threadIdx.x;
    for (int i = tid; i < 4096; i += 256) wks[i] = w_k[i];
    if (tid < 256) wps[tid] = w_pos[tid];
    if (tid < 64)  bps[tid] = b_pos[tid];
    __syncthreads();

    {   // M[o][d] = sum_c W_k[o][c] * W_pos[c][d]
        int o = tid >> 2, d = tid & 3;
        float m = 0.f;
        #pragma unroll 8
        for (int c = 0; c < 64; c++) m += wks[o * 64 + c] * wps[c * 4 + d];
        Ms[tid] = m;
    }
    if (tid < 64) {   // bb[o] = sum_c W_k[o][c] * b_pos[c]
        float m = 0.f;
        #pragma unroll 8
        for (int c = 0; c < 64; c++) m += wks[tid * 64 + c] * bps[c];
        bbs[tid] = m;
    }
    __syncthreads();

    const int b = blockIdx.x >> 6;                  // 64 blocks per batch
    const int n = ((blockIdx.x & 63) << 8) + tid;   // 256 points per block

    float qk[64];
    #pragma unroll
    for (int c = 0; c < 64; c++) qk[c] = 0.f;
    float qp0 = 0.f, qp1 = 0.f, qp2 = 0.f, qp3 = 0.f, qb = 0.f;

    for (int o = 0; o < 64; o++) {
        float qv = point[(size_t)(b * DIM + o) * NPTS + n] * QSCALE;
        const float4* wr = reinterpret_cast<const float4*>(wks + o * 64);
        #pragma unroll
        for (int c4 = 0; c4 < 16; c4++) {
            float4 w = wr[c4];
            qk[c4 * 4 + 0] += w.x * qv;
            qk[c4 * 4 + 1] += w.y * qv;
            qk[c4 * 4 + 2] += w.z * qv;
            qk[c4 * 4 + 3] += w.w * qv;
        }
        qp0 += Ms[o * 4 + 0] * qv;
        qp1 += Ms[o * 4 + 1] * qv;
        qp2 += Ms[o * 4 + 2] * qv;
        qp3 += Ms[o * 4 + 3] * qv;
        qb  += bbs[o] * qv;
    }

    float4* dst = reinterpret_cast<float4*>(g_qk + ((size_t)b * NPTS + n) * DIM);
    #pragma unroll
    for (int c4 = 0; c4 < 16; c4++)
        dst[c4] = make_float4(qk[c4*4+0], qk[c4*4+1], qk[c4*4+2], qk[c4*4+3]);
    reinterpret_cast<float4*>(g_qp)[(size_t)b * NPTS + n] = make_float4(qp0, qp1, qp2, qp3);
    g_qb[(size_t)b * NPTS + n] = qb;
}

// ============================================================================
// K2: attention main kernel (no ncost staging; gmem double-read, L2-hit)
// ============================================================================
__global__ void __launch_bounds__(NTHREADS, 3)
k_attn(const float* __restrict__ xyz,        // [B,3,N]
       const float* __restrict__ nxyz,       // [B,3,N,S]
       const float* __restrict__ ncost,      // [B,C,N,S]
       const float* __restrict__ w_v,        // [64,64] [o][c]
       float* __restrict__ out)              // [B,C,N]
{
    __shared__ float wvT[64 * 68];   // [c*68+o]  transposed, float4-aligned rows
    __shared__ float qks[PP * 68];   // [p*68+c]
    __shared__ float qac[PP * 68];   // [p*68+c]
    __shared__ float nxs[768];       // [d*256 + p*16 + s]
    __shared__ float xs[48];         // [d*16 + p]
    __shared__ float qps[64];        // [p*4+d]
    __shared__ float qbs[16];        // [p]

    const int tid = threadIdx.x;
    const int blk = blockIdx.x;
    const int b   = blk >> 8;                // 256 blocks per batch
    const int t0  = (blk & 255) * TPB;

    // W_v transpose: once per block
    for (int i = tid; i < 4096; i += NTHREADS) {
        int o = i >> 6, c = i & 63;
        wvT[c * 68 + o] = w_v[i];
    }

    const int p = tid >> 4, s = tid & 15;    // 16 lanes per point, 2 points/warp

    for (int t = 0; t < TPB; t++) {
        const int n0 = (t0 + t) * PP;

        // ---------------- per-tile loads ----------------
        if (tid < 48) {
            int d = tid >> 4, pp = tid & 15;
            xs[tid] = xyz[(size_t)(b * 3 + d) * NPTS + n0 + pp];
        }
        for (int i = tid; i < 768; i += NTHREADS) {
            int d = i >> 8, j = i & 255;
            nxs[i] = nxyz[((size_t)(b * 3 + d) * NPTS + n0) * NS + j];
        }
        {   // qk tile: [16 pts][64] contiguous in g_qk
            int pp = tid >> 4, c4 = tid & 15;
            float4 v = reinterpret_cast<const float4*>(
                g_qk + ((size_t)b * NPTS + n0 + pp) * DIM)[c4];
            float* d4 = qks + pp * 68 + c4 * 4;
            reinterpret_cast<float4*>(d4)[0] = v;
        }
        if (tid < 64) qps[tid] = g_qp[((size_t)b * NPTS + n0) * 4 + tid];
        if (tid < 16) qbs[tid] = g_qb[(size_t)b * NPTS + n0 + tid];
        __syncthreads();

        // ---------------- logits (direct coalesced gmem read of ncost) -----
        float w;
        {
            float dx = xs[p]      - nxs[        p * 16 + s];
            float dy = xs[16 + p] - nxs[256 + p * 16 + s];
            float dz = xs[32 + p] - nxs[512 + p * 16 + s];
            float nrm = sqrtf(dx * dx + dy * dy + dz * dz);
            float a = qbs[p] + qps[p * 4 + 0] * dx + qps[p * 4 + 1] * dy
                             + qps[p * 4 + 2] * dz + qps[p * 4 + 3] * nrm;
            const float* qkp = qks + p * 68;
            const float* ncp = ncost + ((size_t)b * DIM * NPTS + n0 + p) * NS + s;
            #pragma unroll 8
            for (int c = 0; c < 64; c++)
                a += qkp[c] * __ldg(ncp + (size_t)c * (NPTS * NS));

            // softmax across 16 lanes of this point
            float m = a;
            #pragma unroll
            for (int off = 8; off; off >>= 1)
                m = fmaxf(m, __shfl_xor_sync(0xffffffffu, m, off, 16));
            float e = __expf(a - m);
            float den = e;
            #pragma unroll
            for (int off = 8; off; off >>= 1)
                den += __shfl_xor_sync(0xffffffffu, den, off, 16);
            w = e / den;
        }

        // gather the 16 softmax weights of this point
        float w16[16];
        #pragma unroll
        for (int j = 0; j < 16; j++)
            w16[j] = __shfl_sync(0xffffffffu, w, j, 16);

        // ---------------- weighted sum over s (second read; L2-hot) --------
        {
            float ac0 = 0.f, ac1 = 0.f, ac2 = 0.f, ac3 = 0.f;
            #pragma unroll
            for (int k = 0; k < 4; k++) {
                int c = s + 16 * k;
                const float4* row = reinterpret_cast<const float4*>(
                    ncost + ((size_t)(b * DIM + c) * NPTS + n0 + p) * NS);
                float acc = 0.f;
                #pragma unroll
                for (int q4 = 0; q4 < 4; q4++) {
                    float4 v = __ldg(row + q4);
                    acc += w16[q4*4+0]*v.x + w16[q4*4+1]*v.y
                         + w16[q4*4+2]*v.z + w16[q4*4+3]*v.w;
                }
                if (k == 0) ac0 = acc; else if (k == 1) ac1 = acc;
                else if (k == 2) ac2 = acc; else ac3 = acc;
            }
            qac[p * 68 + s     ] = ac0;
            qac[p * 68 + s + 16] = ac1;
            qac[p * 68 + s + 32] = ac2;
            qac[p * 68 + s + 48] = ac3;
        }
        __syncthreads();

        // ---------------- out = W_v . acc ----------------
        {
            const int po = tid & 15;
            const int ob = (tid >> 4) * 4;
            float r0 = 0.f, r1 = 0.f, r2 = 0.f, r3 = 0.f;
            const float* accp = qac + po * 68;
            #pragma unroll 8
            for (int c = 0; c < 64; c++) {
                float av = accp[c];
                float4 wv4 = reinterpret_cast<const float4*>(wvT + c * 68 + ob)[0];
                r0 += av * wv4.x; r1 += av * wv4.y;
                r2 += av * wv4.z; r3 += av * wv4.w;
            }
            size_t ob_base = (size_t)(b * DIM + ob) * NPTS + n0 + po;
            out[ob_base              ] = r0;
            out[ob_base + 1ull * NPTS] = r1;
            out[ob_base + 2ull * NPTS] = r2;
            out[ob_base + 3ull * NPTS] = r3;
        }
        __syncthreads();   // protect qks/qac/nxs/xs before next tile
    }
}

// ============================================================================
extern "C" void kernel_launch(void* const* d_in, const int* in_sizes, int n_in,
                              void* d_out, int out_size) {
    (void)in_sizes; (void)n_in; (void)out_size;
    const float* xyz    = (const float*)d_in[0];
    const float* nxyz   = (const float*)d_in[1];
    const float* point  = (const float*)d_in[2];
    // d_in[3] = neighbor_points: unused by the reference math
    const float* ncost  = (const float*)d_in[4];
    const float* w_k    = (const float*)d_in[5];
    const float* w_v    = (const float*)d_in[6];
    const float* w_pos  = (const float*)d_in[7];
    const float* b_pos  = (const float*)d_in[8];
    float* out = (float*)d_out;

    k_precompute<<<NB * (NPTS / 256), 256>>>(point, w_k, w_pos, b_pos);
    k_attn<<<NB * (NPTS / PP) / TPB, NTHREADS>>>(xyz, nxyz, ncost, w_v, out);
}

// round 14
// speedup vs baseline: 1.2078x; 1.2078x over previous
#include <cuda_runtime.h>

// Problem constants (fixed shapes)
#define DIM      64
#define NS       16
#define PP       16          // points per tile (k_attn)
#define TPB      4           // tiles per block (k_attn)
#define NTHREADS 256
#define NPTS     16384
#define NB       4
#define QSCALE   0.125f      // 64^-0.5
#define K1_PTS   128         // points per block in K1

// ---------------- device scratch (static; no runtime alloc) ----------------
__device__ float g_qk[(size_t)NB * NPTS * DIM];   // [b][n][c]
__device__ float g_qp[(size_t)NB * NPTS * 4];     // [b][n][d]
__device__ float g_qb[(size_t)NB * NPTS];         // [b][n]

// ============================================================================
// K1: qk = W_k^T q, qp = (W_k W_pos)^T q, qb = q.(W_k b_pos)   (all * QSCALE)
// 2 threads per point, 32 output channels each; q staged via smem.
// ============================================================================
__global__ void __launch_bounds__(256, 3)
k_precompute(const float* __restrict__ point,   // [B,C,N]
             const float* __restrict__ w_k,     // [64,64] [o][c]
             const float* __restrict__ w_pos,   // [64,4]  [c][d]
             const float* __restrict__ b_pos)   // [64]
{
    __shared__ float wks[4096];          // [o*64+c]
    __shared__ float qs[64 * K1_PTS];    // [o*128 + n]  scaled q tile
    __shared__ float wps[256];
    __shared__ float bps[64];
    __shared__ float Ms[256];            // M = W_k W_pos [o*4+d]
    __shared__ float bbs[64];            // bb = W_k b_pos [o]

    const int tid = threadIdx.x;
    for (int i = tid; i < 4096; i += 256) wks[i] = w_k[i];
    if (tid < 256) wps[tid] = w_pos[tid];
    if (tid < 64)  bps[tid] = b_pos[tid];
    __syncthreads();

    {   // M[o][d], bb[o]
        int o = tid >> 2, d = tid & 3;
        float m = 0.f;
        #pragma unroll 8
        for (int c = 0; c < 64; c++) m += wks[o * 64 + c] * wps[c * 4 + d];
        Ms[tid] = m;
    }
    if (tid < 64) {
        float m = 0.f;
        #pragma unroll 8
        for (int c = 0; c < 64; c++) m += wks[tid * 64 + c] * bps[c];
        bbs[tid] = m;
    }

    const int b  = blockIdx.x >> 7;                 // 128 blocks per batch
    const int n0 = (blockIdx.x & 127) * K1_PTS;

    // stage q tile (coalesced, high MLP)
    for (int i = tid; i < 64 * K1_PTS; i += 256) {
        int o = i >> 7, n = i & (K1_PTS - 1);
        qs[i] = point[(size_t)(b * DIM + o) * NPTS + n0 + n] * QSCALE;
    }
    __syncthreads();

    const int pt   = tid >> 1;          // 0..127
    const int half = tid & 1;
    const int c0   = half * 32;

    float qk[32];
    #pragma unroll
    for (int j = 0; j < 32; j++) qk[j] = 0.f;
    float e0 = 0.f, e1 = 0.f, e2 = 0.f, e3 = 0.f;   // half0: qp; half1: e0=qb

    #pragma unroll 4
    for (int o = 0; o < 64; o++) {
        float qv = qs[o * K1_PTS + pt];
        const float4* wr = reinterpret_cast<const float4*>(wks + o * 64 + c0);
        #pragma unroll
        for (int j4 = 0; j4 < 8; j4++) {
            float4 w = wr[j4];
            qk[j4*4+0] += w.x * qv;
            qk[j4*4+1] += w.y * qv;
            qk[j4*4+2] += w.z * qv;
            qk[j4*4+3] += w.w * qv;
        }
        if (half == 0) {
            e0 += Ms[o * 4 + 0] * qv;
            e1 += Ms[o * 4 + 1] * qv;
            e2 += Ms[o * 4 + 2] * qv;
            e3 += Ms[o * 4 + 3] * qv;
        } else {
            e0 += bbs[o] * qv;
        }
    }

    float4* dst = reinterpret_cast<float4*>(
        g_qk + ((size_t)b * NPTS + n0 + pt) * DIM + c0);
    #pragma unroll
    for (int j4 = 0; j4 < 8; j4++)
        dst[j4] = make_float4(qk[j4*4+0], qk[j4*4+1], qk[j4*4+2], qk[j4*4+3]);

    if (half == 0)
        reinterpret_cast<float4*>(g_qp)[(size_t)b * NPTS + n0 + pt] =
            make_float4(e0, e1, e2, e3);
    else
        g_qb[(size_t)b * NPTS + n0 + pt] = e0;
}

// ============================================================================
// K2: attention (single DRAM read of ncost via smem staging, precomputed qk)
// ============================================================================
__global__ void __launch_bounds__(NTHREADS, 2)
k_attn(const float* __restrict__ xyz,        // [B,3,N]
       const float* __restrict__ nxyz,       // [B,3,N,S]
       const float* __restrict__ ncost,      // [B,C,N,S]
       const float* __restrict__ w_v,        // [64,64] [o][c]
       float* __restrict__ out)              // [B,C,N]
{
    __shared__ float wvT[64 * 68];   // [c*68+o] transposed, float4-aligned rows
    __shared__ float ncs[64 * 257];  // [c*257 + p*16 + s]
    __shared__ float qks[PP * 68];   // [p*68+c]
    __shared__ float qac[PP * 68];   // [p*68+c]
    __shared__ float nxs[768];       // [d*256 + p*16 + s]
    __shared__ float xs[48];
    __shared__ float qps[64];
    __shared__ float qbs[16];

    const int tid = threadIdx.x;
    const int blk = blockIdx.x;
    const int b   = blk >> 8;                // 256 blocks per batch
    const int t0  = (blk & 255) * TPB;

    // W_v transpose once per block (8-way conflict on store; amortized)
    for (int i = tid; i < 4096; i += NTHREADS) {
        int o = i >> 6, c = i & 63;
        wvT[c * 68 + o] = w_v[i];
    }

    const int p = tid >> 4, s = tid & 15;    // 16 lanes per point

    for (int t = 0; t < TPB; t++) {
        const int n0 = (t0 + t) * PP;

        // ---------------- per-tile loads ----------------
        if (tid < 48) {
            int d = tid >> 4, pp = tid & 15;
            xs[tid] = xyz[(size_t)(b * 3 + d) * NPTS + n0 + pp];
        }
        for (int i = tid; i < 768; i += NTHREADS) {
            int d = i >> 8, j = i & 255;
            nxs[i] = nxyz[((size_t)(b * 3 + d) * NPTS + n0) * NS + j];
        }
        {   // qk tile
            int pp = tid >> 4, c4 = tid & 15;
            float4 v = reinterpret_cast<const float4*>(
                g_qk + ((size_t)b * NPTS + n0 + pp) * DIM)[c4];
            reinterpret_cast<float4*>(qks + pp * 68 + c4 * 4)[0] = v;
        }
        if (tid < 64) qps[tid] = g_qp[((size_t)b * NPTS + n0) * 4 + tid];
        if (tid < 16) qbs[tid] = g_qb[(size_t)b * NPTS + n0 + tid];
        {   // ncost tile: one coalesced DRAM read, staged
            const float4* src = reinterpret_cast<const float4*>(ncost);
            #pragma unroll 4
            for (int i = tid; i < 4096; i += NTHREADS) {
                int c = i >> 6, f = i & 63;
                size_t base4 = ((size_t)(b * DIM + c) * NPTS + n0) * 4;
                float4 v = src[base4 + f];
                float* dst = ncs + c * 257 + f * 4;
                dst[0] = v.x; dst[1] = v.y; dst[2] = v.z; dst[3] = v.w;
            }
        }
        __syncthreads();

        // ---------------- logits + softmax ----------------
        float w;
        {
            float dx = xs[p]      - nxs[        p * 16 + s];
            float dy = xs[16 + p] - nxs[256 + p * 16 + s];
            float dz = xs[32 + p] - nxs[512 + p * 16 + s];
            float nrm = sqrtf(dx * dx + dy * dy + dz * dz);
            float a = qbs[p] + qps[p * 4 + 0] * dx + qps[p * 4 + 1] * dy
                             + qps[p * 4 + 2] * dz + qps[p * 4 + 3] * nrm;
            const float4* qk4 = reinterpret_cast<const float4*>(qks + p * 68);
            const float* ncp = ncs + p * 16 + s;
            #pragma unroll
            for (int c4 = 0; c4 < 16; c4++) {
                float4 qv = qk4[c4];
                a += qv.x * ncp[(c4 * 4 + 0) * 257]
                   + qv.y * ncp[(c4 * 4 + 1) * 257]
                   + qv.z * ncp[(c4 * 4 + 2) * 257]
                   + qv.w * ncp[(c4 * 4 + 3) * 257];
            }
            float m = a;
            #pragma unroll
            for (int off = 8; off; off >>= 1)
                m = fmaxf(m, __shfl_xor_sync(0xffffffffu, m, off, 16));
            float e = __expf(a - m);
            float den = e;
            #pragma unroll
            for (int off = 8; off; off >>= 1)
                den += __shfl_xor_sync(0xffffffffu, den, off, 16);
            w = e / den;
        }

        // ---------------- weighted sum over s ----------------
        {
            float ac0 = 0.f, ac1 = 0.f, ac2 = 0.f, ac3 = 0.f;
            #pragma unroll
            for (int s2 = 0; s2 < 16; s2++) {
                float ws = __shfl_sync(0xffffffffu, w, s2, 16);
                const float* row = ncs + p * 16 + s2;
                ac0 += ws * row[(s     ) * 257];
                ac1 += ws * row[(s + 16) * 257];
                ac2 += ws * row[(s + 32) * 257];
                ac3 += ws * row[(s + 48) * 257];
            }
            qac[p * 68 + s     ] = ac0;
            qac[p * 68 + s + 16] = ac1;
            qac[p * 68 + s + 32] = ac2;
            qac[p * 68 + s + 48] = ac3;
        }
        __syncthreads();

        // ---------------- out = W_v . acc ----------------
        {
            const int po = tid & 15;
            const int ob = (tid >> 4) * 4;
            float r0 = 0.f, r1 = 0.f, r2 = 0.f, r3 = 0.f;
            const float4* acc4 = reinterpret_cast<const float4*>(qac + po * 68);
            #pragma unroll
            for (int c4 = 0; c4 < 16; c4++) {
                float4 av = acc4[c4];
                float4 w0 = reinterpret_cast<const float4*>(wvT + (c4*4+0) * 68 + ob)[0];
                float4 w1 = reinterpret_cast<const float4*>(wvT + (c4*4+1) * 68 + ob)[0];
                float4 w2 = reinterpret_cast<const float4*>(wvT + (c4*4+2) * 68 + ob)[0];
                float4 w3 = reinterpret_cast<const float4*>(wvT + (c4*4+3) * 68 + ob)[0];
                r0 += av.x*w0.x + av.y*w1.x + av.z*w2.x + av.w*w3.x;
                r1 += av.x*w0.y + av.y*w1.y + av.z*w2.y + av.w*w3.y;
                r2 += av.x*w0.z + av.y*w1.z + av.z*w2.z + av.w*w3.z;
                r3 += av.x*w0.w + av.y*w1.w + av.z*w2.w + av.w*w3.w;
            }
            size_t ob_base = (size_t)(b * DIM + ob) * NPTS + n0 + po;
            out[ob_base              ] = r0;
            out[ob_base + 1ull * NPTS] = r1;
            out[ob_base + 2ull * NPTS] = r2;
            out[ob_base + 3ull * NPTS] = r3;
        }
        __syncthreads();   // protect smem before next tile's staging
    }
}

// ============================================================================
extern "C" void kernel_launch(void* const* d_in, const int* in_sizes, int n_in,
                              void* d_out, int out_size) {
    (void)in_sizes; (void)n_in; (void)out_size;
    const float* xyz    = (const float*)d_in[0];
    const float* nxyz   = (const float*)d_in[1];
    const float* point  = (const float*)d_in[2];
    // d_in[3] = neighbor_points: unused by the reference math
    const float* ncost  = (const float*)d_in[4];
    const float* w_k    = (const float*)d_in[5];
    const float* w_v    = (const float*)d_in[6];
    const float* w_pos  = (const float*)d_in[7];
    const float* b_pos  = (const float*)d_in[8];
    float* out = (float*)d_out;

    k_precompute<<<NB * (NPTS / K1_PTS), 256>>>(point, w_k, w_pos, b_pos);
    k_attn<<<NB * (NPTS / PP) / TPB, NTHREADS>>>(xyz, nxyz, ncost, w_v, out);
}

// round 15
// speedup vs baseline: 1.2500x; 1.0350x over previous
#include <cuda_runtime.h>

// Problem constants (fixed shapes)
#define DIM      64
#define NS       16
#define PP       16          // points per tile (k_attn)
#define TPB      4           // tiles per block (k_attn)
#define NTHREADS 256
#define NPTS     16384
#define NB       4
#define QSCALE   0.125f      // 64^-0.5
#define K1_PTS   128         // points per block in K1
#define NCR      260         // ncs row stride (floats): 16B-aligned rows, 2-way acc conflict

// ---------------- device scratch (static; no runtime alloc) ----------------
__device__ float g_qk[(size_t)NB * NPTS * DIM];   // [b][n][c]
__device__ float g_qp[(size_t)NB * NPTS * 4];     // [b][n][d]
__device__ float g_qb[(size_t)NB * NPTS];         // [b][n]

// ============================================================================
// K1: qk = W_k^T q, qp = (W_k W_pos)^T q, qb = q.(W_k b_pos)   (all * QSCALE)
// 2 threads per point, 32 output channels each; q staged via smem.
// occupancy 2 (not 3!) so qk[32] stays in registers — no spills.
// ============================================================================
__global__ void __launch_bounds__(256, 2)
k_precompute(const float* __restrict__ point,   // [B,C,N]
             const float* __restrict__ w_k,     // [64,64] [o][c]
             const float* __restrict__ w_pos,   // [64,4]  [c][d]
             const float* __restrict__ b_pos)   // [64]
{
    __shared__ float wks[4096];          // [o*64+c]
    __shared__ float qs[64 * K1_PTS];    // [o*128 + n]  scaled q tile
    __shared__ float wps[256];
    __shared__ float bps[64];
    __shared__ float Ms[256];            // M = W_k W_pos [o*4+d]
    __shared__ float bbs[64];            // bb = W_k b_pos [o]

    const int tid = threadIdx.x;
    for (int i = tid; i < 4096; i += 256) wks[i] = w_k[i];
    if (tid < 256) wps[tid] = w_pos[tid];
    if (tid < 64)  bps[tid] = b_pos[tid];
    __syncthreads();

    {   // M[o][d]
        int o = tid >> 2, d = tid & 3;
        float m = 0.f;
        #pragma unroll 8
        for (int c = 0; c < 64; c++) m += wks[o * 64 + c] * wps[c * 4 + d];
        Ms[tid] = m;
    }
    if (tid < 64) {   // bb[o]
        float m = 0.f;
        #pragma unroll 8
        for (int c = 0; c < 64; c++) m += wks[tid * 64 + c] * bps[c];
        bbs[tid] = m;
    }

    const int b  = blockIdx.x >> 7;                 // 128 blocks per batch
    const int n0 = (blockIdx.x & 127) * K1_PTS;

    // stage q tile (coalesced, high MLP)
    for (int i = tid; i < 64 * K1_PTS; i += 256) {
        int o = i >> 7, n = i & (K1_PTS - 1);
        qs[i] = point[(size_t)(b * DIM + o) * NPTS + n0 + n] * QSCALE;
    }
    __syncthreads();

    const int pt   = tid >> 1;          // 0..127
    const int half = tid & 1;
    const int c0   = half * 32;

    float qk[32];
    #pragma unroll
    for (int j = 0; j < 32; j++) qk[j] = 0.f;
    float e0 = 0.f, e1 = 0.f, e2 = 0.f, e3 = 0.f;   // half0: qp; half1: e0=qb

    #pragma unroll 4
    for (int o = 0; o < 64; o++) {
        float qv = qs[o * K1_PTS + pt];
        const float4* wr = reinterpret_cast<const float4*>(wks + o * 64 + c0);
        #pragma unroll
        for (int j4 = 0; j4 < 8; j4++) {
            float4 w = wr[j4];
            qk[j4*4+0] += w.x * qv;
            qk[j4*4+1] += w.y * qv;
            qk[j4*4+2] += w.z * qv;
            qk[j4*4+3] += w.w * qv;
        }
        if (half == 0) {
            e0 += Ms[o * 4 + 0] * qv;
            e1 += Ms[o * 4 + 1] * qv;
            e2 += Ms[o * 4 + 2] * qv;
            e3 += Ms[o * 4 + 3] * qv;
        } else {
            e0 += bbs[o] * qv;
        }
    }

    float4* dst = reinterpret_cast<float4*>(
        g_qk + ((size_t)b * NPTS + n0 + pt) * DIM + c0);
    #pragma unroll
    for (int j4 = 0; j4 < 8; j4++)
        dst[j4] = make_float4(qk[j4*4+0], qk[j4*4+1], qk[j4*4+2], qk[j4*4+3]);

    if (half == 0)
        reinterpret_cast<float4*>(g_qp)[(size_t)b * NPTS + n0 + pt] =
            make_float4(e0, e1, e2, e3);
    else
        g_qb[(size_t)b * NPTS + n0 + pt] = e0;
}

// ============================================================================
// K2: attention (single DRAM read of ncost via smem staging, precomputed qk)
// ncs stride 260: staging stores are STS.128 conflict-free.
// ============================================================================
__global__ void __launch_bounds__(NTHREADS, 2)
k_attn(const float* __restrict__ xyz,        // [B,3,N]
       const float* __restrict__ nxyz,       // [B,3,N,S]
       const float* __restrict__ ncost,      // [B,C,N,S]
       const float* __restrict__ w_v,        // [64,64] [o][c]
       float* __restrict__ out)              // [B,C,N]
{
    __shared__ float wvT[64 * 68];   // [c*68+o] transposed, float4-aligned rows
    __shared__ float ncs[64 * NCR];  // [c*260 + p*16 + s]
    __shared__ float qks[PP * 68];   // [p*68+c]
    __shared__ float qac[PP * 68];   // [p*68+c]
    __shared__ float nxs[768];       // [d*256 + p*16 + s]
    __shared__ float xs[48];
    __shared__ float qps[64];
    __shared__ float qbs[16];

    const int tid = threadIdx.x;
    const int blk = blockIdx.x;
    const int b   = blk >> 8;                // 256 blocks per batch
    const int t0  = (blk & 255) * TPB;

    // W_v transpose once per block
    for (int i = tid; i < 4096; i += NTHREADS) {
        int o = i >> 6, c = i & 63;
        wvT[c * 68 + o] = w_v[i];
    }

    const int p = tid >> 4, s = tid & 15;    // 16 lanes per point

    for (int t = 0; t < TPB; t++) {
        const int n0 = (t0 + t) * PP;

        // ---------------- per-tile loads ----------------
        if (tid < 48) {
            int d = tid >> 4, pp = tid & 15;
            xs[tid] = xyz[(size_t)(b * 3 + d) * NPTS + n0 + pp];
        }
        for (int i = tid; i < 768; i += NTHREADS) {
            int d = i >> 8, j = i & 255;
            nxs[i] = nxyz[((size_t)(b * 3 + d) * NPTS + n0) * NS + j];
        }
        {   // qk tile
            int pp = tid >> 4, c4 = tid & 15;
            float4 v = reinterpret_cast<const float4*>(
                g_qk + ((size_t)b * NPTS + n0 + pp) * DIM)[c4];
            reinterpret_cast<float4*>(qks + pp * 68 + c4 * 4)[0] = v;
        }
        if (tid < 64) qps[tid] = g_qp[((size_t)b * NPTS + n0) * 4 + tid];
        if (tid < 16) qbs[tid] = g_qb[(size_t)b * NPTS + n0 + tid];
        {   // ncost tile: one coalesced DRAM read, STS.128 conflict-free
            const float4* src = reinterpret_cast<const float4*>(ncost);
            #pragma unroll 4
            for (int i = tid; i < 4096; i += NTHREADS) {
                int c = i >> 6, f = i & 63;
                size_t base4 = ((size_t)(b * DIM + c) * NPTS + n0) * 4;
                float4 v = src[base4 + f];
                reinterpret_cast<float4*>(ncs + c * NCR)[f] = v;
            }
        }
        __syncthreads();

        // ---------------- logits + softmax ----------------
        float w;
        {
            float dx = xs[p]      - nxs[        p * 16 + s];
            float dy = xs[16 + p] - nxs[256 + p * 16 + s];
            float dz = xs[32 + p] - nxs[512 + p * 16 + s];
            float nrm = sqrtf(dx * dx + dy * dy + dz * dz);
            float a = qbs[p] + qps[p * 4 + 0] * dx + qps[p * 4 + 1] * dy
                             + qps[p * 4 + 2] * dz + qps[p * 4 + 3] * nrm;
            const float4* qk4 = reinterpret_cast<const float4*>(qks + p * 68);
            const float* ncp = ncs + p * 16 + s;
            #pragma unroll
            for (int c4 = 0; c4 < 16; c4++) {
                float4 qv = qk4[c4];
                a += qv.x * ncp[(c4 * 4 + 0) * NCR]
                   + qv.y * ncp[(c4 * 4 + 1) * NCR]
                   + qv.z * ncp[(c4 * 4 + 2) * NCR]
                   + qv.w * ncp[(c4 * 4 + 3) * NCR];
            }
            float m = a;
            #pragma unroll
            for (int off = 8; off; off >>= 1)
                m = fmaxf(m, __shfl_xor_sync(0xffffffffu, m, off, 16));
            float e = __expf(a - m);
            float den = e;
            #pragma unroll
            for (int off = 8; off; off >>= 1)
                den += __shfl_xor_sync(0xffffffffu, den, off, 16);
            w = e / den;
        }

        // ---------------- weighted sum over s ----------------
        {
            float ac0 = 0.f, ac1 = 0.f, ac2 = 0.f, ac3 = 0.f;
            #pragma unroll
            for (int s2 = 0; s2 < 16; s2++) {
                float ws = __shfl_sync(0xffffffffu, w, s2, 16);
                const float* row = ncs + p * 16 + s2;
                ac0 += ws * row[(s     ) * NCR];
                ac1 += ws * row[(s + 16) * NCR];
                ac2 += ws * row[(s + 32) * NCR];
                ac3 += ws * row[(s + 48) * NCR];
            }
            qac[p * 68 + s     ] = ac0;
            qac[p * 68 + s + 16] = ac1;
            qac[p * 68 + s + 32] = ac2;
            qac[p * 68 + s + 48] = ac3;
        }
        __syncthreads();

        // ---------------- out = W_v . acc ----------------
        {
            const int po = tid & 15;
            const int ob = (tid >> 4) * 4;
            float r0 = 0.f, r1 = 0.f, r2 = 0.f, r3 = 0.f;
            const float4* acc4 = reinterpret_cast<const float4*>(qac + po * 68);
            #pragma unroll
            for (int c4 = 0; c4 < 16; c4++) {
                float4 av = acc4[c4];
                float4 w0 = reinterpret_cast<const float4*>(wvT + (c4*4+0) * 68 + ob)[0];
                float4 w1 = reinterpret_cast<const float4*>(wvT + (c4*4+1) * 68 + ob)[0];
                float4 w2 = reinterpret_cast<const float4*>(wvT + (c4*4+2) * 68 + ob)[0];
                float4 w3 = reinterpret_cast<const float4*>(wvT + (c4*4+3) * 68 + ob)[0];
                r0 += av.x*w0.x + av.y*w1.x + av.z*w2.x + av.w*w3.x;
                r1 += av.x*w0.y + av.y*w1.y + av.z*w2.y + av.w*w3.y;
                r2 += av.x*w0.z + av.y*w1.z + av.z*w2.z + av.w*w3.z;
                r3 += av.x*w0.w + av.y*w1.w + av.z*w2.w + av.w*w3.w;
            }
            size_t ob_base = (size_t)(b * DIM + ob) * NPTS + n0 + po;
            out[ob_base              ] = r0;
            out[ob_base + 1ull * NPTS] = r1;
            out[ob_base + 2ull * NPTS] = r2;
            out[ob_base + 3ull * NPTS] = r3;
        }
        __syncthreads();   // protect smem before next tile's staging
    }
}

// ============================================================================
extern "C" void kernel_launch(void* const* d_in, const int* in_sizes, int n_in,
                              void* d_out, int out_size) {
    (void)in_sizes; (void)n_in; (void)out_size;
    const float* xyz    = (const float*)d_in[0];
    const float* nxyz   = (const float*)d_in[1];
    const float* point  = (const float*)d_in[2];
    // d_in[3] = neighbor_points: unused by the reference math
    const float* ncost  = (const float*)d_in[4];
    const float* w_k    = (const float*)d_in[5];
    const float* w_v    = (const float*)d_in[6];
    const float* w_pos  = (const float*)d_in[7];
    const float* b_pos  = (const float*)d_in[8];
    float* out = (float*)d_out;

    k_precompute<<<NB * (NPTS / K1_PTS), 256>>>(point, w_k, w_pos, b_pos);
    k_attn<<<NB * (NPTS / PP) / TPB, NTHREADS>>>(xyz, nxyz, ncost, w_v, out);
}